// round 9
// baseline (speedup 1.0000x reference)
#include <cuda_runtime.h>

// MS-SSIM loss, 4 scales. v8:
//  - 64x32 tiles everywhere (halo redundancy 1.97x -> 1.64x), dynamic smem
//    (71.3KB/block, 3 blocks/SM via __launch_bounds__(256,3))
//  - scales 2+3 fused in one launch (s3 blocks acquire-spin on s2's per-plane
//    pool counter, published right after the pool via fence+release atomic)
//  - stage-2 in two 5-load phases to bound register pressure
// Math: f32x2 sum/diff form (s=a+b, d=a-b; conv (s,d) and (s^2,d^2)).

#define NPLANES 48
typedef unsigned long long ull;

// ---- device globals (no allocations allowed) ----
__device__ float  g_acc[4];        // zero-init at load; finalize resets
__device__ int    g_pdone2[NPLANES];
__device__ float2 g_p1[48 * 256 * 256];
__device__ float2 g_p2[48 * 128 * 128];
__device__ float2 g_p3[48 * 64 * 64];

// ---- packed f32x2 helpers ----
__device__ __forceinline__ ull pack2(float lo, float hi) {
    ull r;
    asm("mov.b64 %0, {%1, %2};" : "=l"(r) : "f"(lo), "f"(hi));
    return r;
}
__device__ __forceinline__ void unpack2(ull v, float& lo, float& hi) {
    asm("mov.b64 {%0, %1}, %2;" : "=f"(lo), "=f"(hi) : "l"(v));
}
__device__ __forceinline__ void ffma2(ull& acc, ull a, ull b) {
    asm("fma.rn.f32x2 %0, %1, %2, %0;" : "+l"(acc) : "l"(a), "l"(b));
}
__device__ __forceinline__ ull fmul2(ull a, ull b) {
    ull d;
    asm("mul.rn.f32x2 %0, %1, %2;" : "=l"(d) : "l"(a), "l"(b));
    return d;
}
__device__ __forceinline__ int ld_acquire(const int* p) {
    int v;
    asm volatile("ld.acquire.gpu.global.b32 %0, [%1];" : "=r"(v) : "l"(p) : "memory");
    return v;
}

// Gaussian(11, sigma=1.5), normalized.
#define G_LIST { \
    0.00102838f, 0.00759875f, 0.03600077f, 0.10936070f, 0.21300553f, \
    0.26601172f, \
    0.21300553f, 0.10936070f, 0.03600077f, 0.00759875f, 0.00102838f }

#define TW 64
#define TH 32
#define RPT 8
#define NT 256                 // TW*TH/RPT
#define IH 42                  // TH + 10
#define LW4 20                 // TW/4+4 raw-float4 loads per row (scale 0)
#define NF4 40                 // TW/2+8 float4(=2px) loads per row (pooled)
#define LP 82                  // sSD pitch (row 656B: quad-rotating banks)
#define SLOTS 8                // TW/8 8-wide output groups per row
#define HP 65                  // h12 pitch (row 1040B: quad-rotating banks)

#define SSD_BYTES (IH * LP * 8)            // 27552
#define H12_BYTES (IH * HP * 16)           // 43680
#define SMEM_BYTES (SSD_BYTES + H12_BYTES + 64)

__global__ void __launch_bounds__(NT, 3)
ssim_kernel(const float* __restrict__ A0, const float* __restrict__ B0,
            int scale, int W, int do_pool, int fused)
{
    extern __shared__ __align__(16) char smem_raw[];
    float2     (*sSD)[LP] = reinterpret_cast<float2(*)[LP]>(smem_raw);
    ulonglong2 (*h12)[HP] = reinterpret_cast<ulonglong2(*)[HP]>(smem_raw + SSD_BYTES);
    float* red = reinterpret_cast<float*>(smem_raw + SSD_BYTES + H12_BYTES);

    const float G[11] = G_LIST;
    ull g2[11];
    #pragma unroll
    for (int k = 0; k < 11; k++) g2[k] = pack2(G[k], G[k]);

    const int tid   = threadIdx.x;
    const int plane = blockIdx.z;
    int txi = blockIdx.x, tyi = blockIdx.y;

    if (fused) {
        if (blockIdx.x < 8) {            // scale-2 tile (128x128: 2x4 tiles)
            scale = 2; W = 128; do_pool = 1;
            txi = blockIdx.x & 1; tyi = blockIdx.x >> 1;
        } else {                         // scale-3 tile (64x64: 1x2 tiles)
            scale = 3; W = 64; do_pool = 0;
            txi = 0; tyi = blockIdx.x - 8;
            if (tid == 0) {              // wait for all 8 s2 tiles of this plane
                int ns = 64;
                while (ld_acquire(&g_pdone2[plane]) < 8) {
                    __nanosleep(ns);
                    if (ns < 2048) ns <<= 1;
                }
            }
            __syncthreads();
        }
    }

    const int H = W;
    const float2* P;
    switch (scale) {
        case 1:  P = g_p1; break;
        case 2:  P = g_p2; break;
        default: P = g_p3; break;
    }
    const int tx = txi * TW;
    const int ty = tyi * TH;
    const size_t pbase = (size_t)plane * (size_t)W * (size_t)H;

    // ---- stage 1: load tile + halo as interleaved (s,d) ----
    if (scale == 0) {
        for (int i = tid; i < IH * LW4; i += NT) {
            int r = i / LW4;
            int s = i - r * LW4;
            int gy = ty + r - 5;
            int gx = tx + 4 * s - 8;
            float4 a = make_float4(0.f, 0.f, 0.f, 0.f);
            float4 b = a;
            if ((unsigned)gy < (unsigned)H && (unsigned)gx <= (unsigned)(W - 4)) {
                size_t idx = pbase + (size_t)gy * W + gx;
                a = *reinterpret_cast<const float4*>(A0 + idx);
                b = *reinterpret_cast<const float4*>(B0 + idx);
            }
            float4 lo = make_float4(a.x + b.x, a.x - b.x, a.y + b.y, a.y - b.y);
            float4 hi = make_float4(a.z + b.z, a.z - b.z, a.w + b.w, a.w - b.w);
            *reinterpret_cast<float4*>(&sSD[r][4 * s])     = lo;
            *reinterpret_cast<float4*>(&sSD[r][4 * s + 2]) = hi;
        }
    } else {
        for (int i = tid; i < IH * NF4; i += NT) {
            int r = i / NF4;
            int s = i - r * NF4;
            int gy = ty + r - 5;
            int gx = tx + 2 * s - 8;
            float4 v = make_float4(0.f, 0.f, 0.f, 0.f);
            if ((unsigned)gy < (unsigned)H && (unsigned)gx <= (unsigned)(W - 2)) {
                v = *reinterpret_cast<const float4*>(P + pbase + (size_t)gy * W + gx);
            }
            *reinterpret_cast<float4*>(&sSD[r][2 * s]) = v;
        }
    }
    __syncthreads();

    // ---- fused 2x2 avg-pool for the next scale ((s,d) is linear) ----
    if (do_pool) {
        constexpr int PW = TW / 2, PH = TH / 2;
        float2* PD = (scale == 0) ? g_p1 : (scale == 1) ? g_p2 : g_p3;
        int pW = W >> 1;
        for (int i = tid; i < PW * PH; i += NT) {
            int pr = i / PW;
            int pc = i - pr * PW;
            int r = 5 + 2 * pr;
            int c = 8 + 2 * pc;
            float2 q00 = sSD[r][c],     q01 = sSD[r][c + 1];
            float2 q10 = sSD[r + 1][c], q11 = sSD[r + 1][c + 1];
            float2 o;
            o.x = 0.25f * (q00.x + q01.x + q10.x + q11.x);
            o.y = 0.25f * (q00.y + q01.y + q10.y + q11.y);
            size_t pidx = (size_t)plane * pW * pW
                        + (size_t)((ty >> 1) + pr) * pW + ((tx >> 1) + pc);
            PD[pidx] = o;
        }
        if (fused && scale == 2) {       // publish pool for this plane's s3 waiters
            __threadfence();
            __syncthreads();
            if (tid == 0) atomicAdd(&g_pdone2[plane], 1);
        }
    }

    // ---- stage 2: horizontal 11-tap pass, 8 outputs/thread-group,
    //      two 5-load phases to bound register pressure ----
    for (int i = tid; i < IH * SLOTS; i += NT) {
        int r  = i % IH;                 // row-fastest: conflict-free phases
        int sl = i / IH;
        int c0 = 8 * sl;
        ull a1[8], a2[8];
        #pragma unroll
        for (int j = 0; j < 8; j++) { a1[j] = 0ull; a2[j] = 0ull; }
        {
            ull w[10];                   // cols c0+2 .. c0+11
            #pragma unroll
            for (int q = 0; q < 5; q++) {
                ulonglong2 u = *reinterpret_cast<const ulonglong2*>(&sSD[r][c0 + 2 + 2 * q]);
                w[2 * q] = u.x; w[2 * q + 1] = u.y;
            }
            #pragma unroll
            for (int m = 0; m < 9; m++) {    // col c0+3+m = w[m+1]
                ull v  = w[m + 1];
                ull v2 = fmul2(v, v);
                #pragma unroll
                for (int j = 0; j < 8; j++) {
                    int k = m - j;
                    if (k >= 0 && k < 11) {
                        ffma2(a1[j], v,  g2[k]);
                        ffma2(a2[j], v2, g2[k]);
                    }
                }
            }
        }
        {
            ull w[10];                   // cols c0+12 .. c0+21
            #pragma unroll
            for (int q = 0; q < 5; q++) {
                ulonglong2 u = *reinterpret_cast<const ulonglong2*>(&sSD[r][c0 + 12 + 2 * q]);
                w[2 * q] = u.x; w[2 * q + 1] = u.y;
            }
            #pragma unroll
            for (int m = 9; m < 18; m++) {   // col c0+3+m = w[m-9]
                ull v  = w[m - 9];
                ull v2 = fmul2(v, v);
                #pragma unroll
                for (int j = 0; j < 8; j++) {
                    int k = m - j;
                    if (k >= 0 && k < 11) {
                        ffma2(a1[j], v,  g2[k]);
                        ffma2(a2[j], v2, g2[k]);
                    }
                }
            }
        }
        #pragma unroll
        for (int j = 0; j < 8; j++) {
            h12[r][c0 + j] = make_ulonglong2(a1[j], a2[j]);
        }
    }
    __syncthreads();

    // ---- stage 3: vertical 11-tap pass (f32x2), SSIM map, reduce ----
    float acc = 0.0f;
    {
        const int c  = tid % TW;
        const int r0 = (tid / TW) * RPT;
        ull s1[RPT], s2[RPT];
        #pragma unroll
        for (int j = 0; j < RPT; j++) { s1[j] = 0ull; s2[j] = 0ull; }
        #pragma unroll
        for (int t = 0; t < RPT + 10; t++) {
            ulonglong2 v = h12[r0 + t][c];
            #pragma unroll
            for (int j = 0; j < RPT; j++) {
                int k = t - j;
                if (k >= 0 && k < 11) {
                    ffma2(s1[j], v.x, g2[k]);
                    ffma2(s2[j], v.y, g2[k]);
                }
            }
        }
        const float C1 = 1e-4f;
        const float C2 = 9e-4f;
        #pragma unroll
        for (int j = 0; j < RPT; j++) {
            float mus, mud, es2, ed2;
            unpack2(s1[j], mus, mud);
            unpack2(s2[j], es2, ed2);
            float Aq = mus * mus;
            float Bq = mud * mud;
            float mu12  = 0.25f * (Aq - Bq);            // mu1*mu2
            float musq  = 0.5f  * (Aq + Bq);            // mu1^2+mu2^2
            float sigs  = 0.5f  * (es2 + ed2) - musq;   // sig1^2+sig2^2
            float sig12 = 0.25f * (es2 - ed2) - mu12;   // sig12
            float num = (2.0f * mu12 + C1) * (2.0f * sig12 + C2);
            float den = (musq + C1) * (sigs + C2);
            acc += __fdividef(num, den);
        }
    }

    // ---- block reduction -> one atomic per block ----
    #pragma unroll
    for (int o = 16; o > 0; o >>= 1)
        acc += __shfl_down_sync(0xffffffffu, acc, o);
    if ((tid & 31) == 0) red[tid >> 5] = acc;
    __syncthreads();
    if (tid == 0) {
        float s = 0.f;
        #pragma unroll
        for (int w = 0; w < NT / 32; w++) s += red[w];
        atomicAdd(&g_acc[scale], s);
    }
}

__global__ void finalize_kernel(float* __restrict__ out) {
    int tid = threadIdx.x;
    if (tid < NPLANES) g_pdone2[tid] = 0;    // reset for next graph replay
    if (tid == 0) {
        const float w[4] = {0.0448f, 0.2856f, 0.3001f, 0.2363f};
        float loss = 0.0f;
        float cnt = 48.0f * 512.0f * 512.0f;
        #pragma unroll
        for (int s = 0; s < 4; s++) {
            loss += w[s] * (1.0f - g_acc[s] / cnt);
            cnt *= 0.25f;
        }
        out[0] = loss;
        #pragma unroll
        for (int s = 0; s < 4; s++) g_acc[s] = 0.0f;
    }
}

extern "C" void kernel_launch(void* const* d_in, const int* in_sizes, int n_in,
                              void* d_out, int out_size) {
    const float* img1 = (const float*)d_in[0];
    const float* img2 = (const float*)d_in[1];
    float* out = (float*)d_out;

    cudaFuncSetAttribute(ssim_kernel,
                         cudaFuncAttributeMaxDynamicSharedMemorySize, SMEM_BYTES);

    // scale 0: 512x512, 64x32 tiles
    ssim_kernel<<<dim3(8, 16, NPLANES), NT, SMEM_BYTES>>>(img1, img2, 0, 512, 1, 0);
    // scale 1: 256x256
    ssim_kernel<<<dim3(4, 8, NPLANES), NT, SMEM_BYTES>>>(nullptr, nullptr, 1, 256, 1, 0);
    // scales 2+3 fused: x<8 -> s2 tiles (publish pool), x>=8 -> s3 tiles (spin)
    ssim_kernel<<<dim3(10, 1, NPLANES), NT, SMEM_BYTES>>>(nullptr, nullptr, 2, 128, 1, 1);

    finalize_kernel<<<1, 64>>>(out);
}

// round 10
// speedup vs baseline: 1.0020x; 1.0020x over previous
#include <cuda_runtime.h>

// MS-SSIM loss, 4 scales. v9: v7b tile math (proven 125.7us), restructured as
// TWO launches: (A) scale 0; (B) scales 1+2+3 fused in one flat grid with
// per-plane spin deps (s2 waits s1's pool, s3 waits s2's pool) + in-kernel
// finalize by the last block. Removes 3 launch gaps + the finalize launch and
// overlaps the small-scale tails.
// Math: f32x2 sum/diff form (s=a+b, d=a-b; conv (s,d) and (s^2,d^2)).

#define NPLANES 48
typedef unsigned long long ull;

// ---- device globals (no allocations allowed; zero-init at load) ----
__device__ float  g_acc[4];
__device__ int    g_s1done[NPLANES];
__device__ int    g_s2done[NPLANES];
__device__ int    g_bdone;
__device__ float2 g_p1[48 * 256 * 256];
__device__ float2 g_p2[48 * 128 * 128];
__device__ float2 g_p3[48 * 64 * 64];

// ---- packed f32x2 helpers ----
__device__ __forceinline__ ull pack2(float lo, float hi) {
    ull r;
    asm("mov.b64 %0, {%1, %2};" : "=l"(r) : "f"(lo), "f"(hi));
    return r;
}
__device__ __forceinline__ void unpack2(ull v, float& lo, float& hi) {
    asm("mov.b64 {%0, %1}, %2;" : "=f"(lo), "=f"(hi) : "l"(v));
}
__device__ __forceinline__ void ffma2(ull& acc, ull a, ull b) {
    asm("fma.rn.f32x2 %0, %1, %2, %0;" : "+l"(acc) : "l"(a), "l"(b));
}
__device__ __forceinline__ ull fmul2(ull a, ull b) {
    ull d;
    asm("mul.rn.f32x2 %0, %1, %2;" : "=l"(d) : "l"(a), "l"(b));
    return d;
}
__device__ __forceinline__ int ld_acquire(const int* p) {
    int v;
    asm volatile("ld.acquire.gpu.global.b32 %0, [%1];" : "=r"(v) : "l"(p) : "memory");
    return v;
}

// Gaussian(11, sigma=1.5), normalized.
#define G_LIST { \
    0.00102838f, 0.00759875f, 0.03600077f, 0.10936070f, 0.21300553f, \
    0.26601172f, \
    0.21300553f, 0.10936070f, 0.03600077f, 0.00759875f, 0.00102838f }

// Fixed tile config (v7b's proven s0 config): 32x32, 128 thr, RPT=8.
#define TW 32
#define TH 32
#define RPT 8
#define NT 128
#define IH 42                 // TH + 10
#define LW4 12                // TW/4+4 raw-float4 loads per row (scale 0)
#define NF4 24                // TW/2+8 float4(=2px) loads per row (pooled)
#define LP 50                 // sSD pitch (row 400B: quad-rotating banks)
#define SLOTS 4               // TW/8 8-wide output groups per row
#define HP 33                 // h12 pitch (row 528B: quad-rotating banks)

// Launch-B block ranges (all 32x32 tiles)
#define B_S1 3072             // 64 tiles/plane (256x256)
#define B_S2 768              // 16 tiles/plane (128x128)
#define B_S3 192              //  4 tiles/plane (64x64)
#define B_TOT (B_S1 + B_S2 + B_S3)   // 4032

// ---- shared tile pipeline (identical math to v7b) ----
struct Smem {
    float2     sSD[IH][LP];
    ulonglong2 h12[IH][HP];
    float      red[NT / 32];
};

__device__ __forceinline__ void tile_pipeline(
    Smem& sm, const ull* g2, const float* G,
    const float* A0, const float* B0, const float2* P,
    int scale, int W, int tx, int ty, int plane, int do_pool, int publish)
{
    const int H = W;
    const size_t pbase = (size_t)plane * (size_t)W * (size_t)H;
    const int tid = threadIdx.x;

    // ---- stage 1: load tile + halo as interleaved (s,d) ----
    if (scale == 0) {
        for (int i = tid; i < IH * LW4; i += NT) {
            int r = i / LW4;
            int s = i - r * LW4;
            int gy = ty + r - 5;
            int gx = tx + 4 * s - 8;
            float4 a = make_float4(0.f, 0.f, 0.f, 0.f);
            float4 b = a;
            if ((unsigned)gy < (unsigned)H && (unsigned)gx <= (unsigned)(W - 4)) {
                size_t idx = pbase + (size_t)gy * W + gx;
                a = *reinterpret_cast<const float4*>(A0 + idx);
                b = *reinterpret_cast<const float4*>(B0 + idx);
            }
            float4 lo = make_float4(a.x + b.x, a.x - b.x, a.y + b.y, a.y - b.y);
            float4 hi = make_float4(a.z + b.z, a.z - b.z, a.w + b.w, a.w - b.w);
            *reinterpret_cast<float4*>(&sm.sSD[r][4 * s])     = lo;
            *reinterpret_cast<float4*>(&sm.sSD[r][4 * s + 2]) = hi;
        }
    } else {
        for (int i = tid; i < IH * NF4; i += NT) {
            int r = i / NF4;
            int s = i - r * NF4;
            int gy = ty + r - 5;
            int gx = tx + 2 * s - 8;
            float4 v = make_float4(0.f, 0.f, 0.f, 0.f);
            if ((unsigned)gy < (unsigned)H && (unsigned)gx <= (unsigned)(W - 2)) {
                v = *reinterpret_cast<const float4*>(P + pbase + (size_t)gy * W + gx);
            }
            *reinterpret_cast<float4*>(&sm.sSD[r][2 * s]) = v;
        }
    }
    __syncthreads();

    // ---- fused 2x2 avg-pool for the next scale ((s,d) is linear) ----
    if (do_pool) {
        constexpr int PW = TW / 2, PH = TH / 2;
        float2* PD = (scale == 0) ? g_p1 : (scale == 1) ? g_p2 : g_p3;
        int pW = W >> 1;
        for (int i = tid; i < PW * PH; i += NT) {
            int pr = i / PW;
            int pc = i - pr * PW;
            int r = 5 + 2 * pr;
            int c = 8 + 2 * pc;
            float2 q00 = sm.sSD[r][c],     q01 = sm.sSD[r][c + 1];
            float2 q10 = sm.sSD[r + 1][c], q11 = sm.sSD[r + 1][c + 1];
            float2 o;
            o.x = 0.25f * (q00.x + q01.x + q10.x + q11.x);
            o.y = 0.25f * (q00.y + q01.y + q10.y + q11.y);
            size_t pidx = (size_t)plane * pW * pW
                        + (size_t)((ty >> 1) + pr) * pW + ((tx >> 1) + pc);
            PD[pidx] = o;
        }
        if (publish) {   // make pool visible, then count this tile
            __threadfence();
            __syncthreads();
            if (tid == 0) {
                int* cnt = (scale == 1) ? &g_s1done[plane] : &g_s2done[plane];
                atomicAdd(cnt, 1);
            }
        }
    }

    // ---- stage 2: horizontal 11-tap pass, 8 outputs/thread-group ----
    for (int i = tid; i < IH * SLOTS; i += NT) {
        int r  = i % IH;              // row-fastest map: conflict-free phases
        int sl = i / IH;
        int c0 = 8 * sl;
        ull w[20];                    // cols c0+2 .. c0+21
        #pragma unroll
        for (int q = 0; q < 10; q++) {
            ulonglong2 u = *reinterpret_cast<const ulonglong2*>(&sm.sSD[r][c0 + 2 + 2 * q]);
            w[2 * q]     = u.x;
            w[2 * q + 1] = u.y;
        }
        ull a1[8], a2[8];
        #pragma unroll
        for (int j = 0; j < 8; j++) { a1[j] = 0ull; a2[j] = 0ull; }
        #pragma unroll
        for (int m = 0; m < 18; m++) {   // col c0+3+m = w[m+1]
            ull v  = w[m + 1];
            ull v2 = fmul2(v, v);
            #pragma unroll
            for (int j = 0; j < 8; j++) {
                int k = m - j;
                if (k >= 0 && k < 11) {
                    ffma2(a1[j], v,  g2[k]);
                    ffma2(a2[j], v2, g2[k]);
                }
            }
        }
        #pragma unroll
        for (int j = 0; j < 8; j++) {
            sm.h12[r][c0 + j] = make_ulonglong2(a1[j], a2[j]);
        }
    }
    __syncthreads();

    // ---- stage 3: vertical 11-tap pass (f32x2), SSIM map, reduce ----
    float acc = 0.0f;
    {
        const int c  = tid % TW;
        const int r0 = (tid / TW) * RPT;
        ull s1[RPT], s2[RPT];
        #pragma unroll
        for (int j = 0; j < RPT; j++) { s1[j] = 0ull; s2[j] = 0ull; }
        #pragma unroll
        for (int t = 0; t < RPT + 10; t++) {
            ulonglong2 v = sm.h12[r0 + t][c];
            #pragma unroll
            for (int j = 0; j < RPT; j++) {
                int k = t - j;
                if (k >= 0 && k < 11) {
                    ffma2(s1[j], v.x, g2[k]);
                    ffma2(s2[j], v.y, g2[k]);
                }
            }
        }
        const float C1 = 1e-4f;
        const float C2 = 9e-4f;
        #pragma unroll
        for (int j = 0; j < RPT; j++) {
            float mus, mud, es2, ed2;
            unpack2(s1[j], mus, mud);
            unpack2(s2[j], es2, ed2);
            float Aq = mus * mus;
            float Bq = mud * mud;
            float mu12  = 0.25f * (Aq - Bq);
            float musq  = 0.5f  * (Aq + Bq);
            float sigs  = 0.5f  * (es2 + ed2) - musq;
            float sig12 = 0.25f * (es2 - ed2) - mu12;
            float num = (2.0f * mu12 + C1) * (2.0f * sig12 + C2);
            float den = (musq + C1) * (sigs + C2);
            acc += __fdividef(num, den);
        }
    }

    // ---- block reduction -> one atomic per block ----
    #pragma unroll
    for (int o = 16; o > 0; o >>= 1)
        acc += __shfl_down_sync(0xffffffffu, acc, o);
    if ((tid & 31) == 0) sm.red[tid >> 5] = acc;
    __syncthreads();
    if (tid == 0) {
        float s = 0.f;
        #pragma unroll
        for (int w = 0; w < NT / 32; w++) s += sm.red[w];
        atomicAdd(&g_acc[scale], s);
    }
}

// ---- launch A: scale 0 only ----
__global__ void __launch_bounds__(NT)
ssim_scale0(const float* __restrict__ A0, const float* __restrict__ B0)
{
    __shared__ __align__(16) Smem sm;
    const float G[11] = G_LIST;
    ull g2[11];
    #pragma unroll
    for (int k = 0; k < 11; k++) g2[k] = pack2(G[k], G[k]);

    tile_pipeline(sm, g2, G, A0, B0, nullptr,
                  0, 512, blockIdx.x * TW, blockIdx.y * TH, blockIdx.z,
                  /*do_pool=*/1, /*publish=*/0);
}

// ---- launch B: scales 1+2+3 fused, finalize by last block ----
__global__ void __launch_bounds__(NT)
ssim_small_fused(float* __restrict__ out)
{
    __shared__ __align__(16) Smem sm;
    const float G[11] = G_LIST;
    ull g2[11];
    #pragma unroll
    for (int k = 0; k < 11; k++) g2[k] = pack2(G[k], G[k]);

    const int bid = blockIdx.x;
    const int tid = threadIdx.x;

    int scale, plane, txi, tyi, W, do_pool, publish;
    if (bid < B_S1) {
        scale = 1; W = 256; do_pool = 1; publish = 1;
        plane = bid >> 6; int rem = bid & 63; tyi = rem >> 3; txi = rem & 7;
    } else if (bid < B_S1 + B_S2) {
        int r = bid - B_S1;
        scale = 2; W = 128; do_pool = 1; publish = 1;
        plane = r >> 4; int rem = r & 15; tyi = rem >> 2; txi = rem & 3;
        if (tid == 0) {
            int ns = 64;
            while (ld_acquire(&g_s1done[plane]) < 64) {
                __nanosleep(ns);
                if (ns < 2048) ns <<= 1;
            }
        }
        __syncthreads();
    } else {
        int r = bid - (B_S1 + B_S2);
        scale = 3; W = 64; do_pool = 0; publish = 0;
        plane = r >> 2; int rem = r & 3; tyi = rem >> 1; txi = rem & 1;
        if (tid == 0) {
            int ns = 64;
            while (ld_acquire(&g_s2done[plane]) < 16) {
                __nanosleep(ns);
                if (ns < 2048) ns <<= 1;
            }
        }
        __syncthreads();
    }

    const float2* P = (scale == 1) ? g_p1 : (scale == 2) ? g_p2 : g_p3;
    tile_pipeline(sm, g2, G, nullptr, nullptr, P,
                  scale, W, txi * TW, tyi * TH, plane, do_pool, publish);

    // ---- completion counting; last block finalizes + resets ----
    __syncthreads();
    if (tid == 0) {
        __threadfence();                       // order g_acc add before count
        int d = atomicAdd(&g_bdone, 1);
        if (d == B_TOT - 1) {
            float a0 = atomicAdd(&g_acc[0], 0.0f);   // L2-RMW reads: latest
            float a1 = atomicAdd(&g_acc[1], 0.0f);
            float a2 = atomicAdd(&g_acc[2], 0.0f);
            float a3 = atomicAdd(&g_acc[3], 0.0f);
            const float w[4] = {0.0448f, 0.2856f, 0.3001f, 0.2363f};
            float n0 = 48.0f * 512.0f * 512.0f;
            float loss = w[0] * (1.0f - a0 / n0)
                       + w[1] * (1.0f - a1 / (n0 * 0.25f))
                       + w[2] * (1.0f - a2 / (n0 * 0.0625f))
                       + w[3] * (1.0f - a3 / (n0 * 0.015625f));
            out[0] = loss;
            // reset scheduler state for next graph replay
            #pragma unroll
            for (int s = 0; s < 4; s++) g_acc[s] = 0.0f;
            for (int p = 0; p < NPLANES; p++) { g_s1done[p] = 0; g_s2done[p] = 0; }
            g_bdone = 0;
        }
    }
}

extern "C" void kernel_launch(void* const* d_in, const int* in_sizes, int n_in,
                              void* d_out, int out_size) {
    const float* img1 = (const float*)d_in[0];
    const float* img2 = (const float*)d_in[1];
    float* out = (float*)d_out;

    // A: scale 0 (512x512, 32x32 tiles, 256 tiles/plane)
    ssim_scale0<<<dim3(16, 16, NPLANES), NT>>>(img1, img2);
    // B: scales 1+2+3 fused + in-kernel finalize
    ssim_small_fused<<<B_TOT, NT>>>(out);
}

// round 11
// speedup vs baseline: 1.0364x; 1.0343x over previous
#include <cuda_runtime.h>

// MS-SSIM loss, 4 scales. v10: v7b math; occupancy fix for the dominant
// launches (s0/s1 now 256 thr, RPT=4 -> 40 warps/SM instead of 20);
// finalize folded into the s3 launch (last-block pattern). 4 launches total.
// Math: f32x2 sum/diff form (s=a+b, d=a-b; conv (s,d) and (s^2,d^2)).

#define NPLANES 48
typedef unsigned long long ull;

// ---- device globals (no allocations allowed; zero-init at load) ----
__device__ float  g_acc[4];
__device__ int    g_fdone;
__device__ float2 g_p1[48 * 256 * 256];
__device__ float2 g_p2[48 * 128 * 128];
__device__ float2 g_p3[48 * 64 * 64];

// ---- packed f32x2 helpers ----
__device__ __forceinline__ ull pack2(float lo, float hi) {
    ull r;
    asm("mov.b64 %0, {%1, %2};" : "=l"(r) : "f"(lo), "f"(hi));
    return r;
}
__device__ __forceinline__ void unpack2(ull v, float& lo, float& hi) {
    asm("mov.b64 {%0, %1}, %2;" : "=f"(lo), "=f"(hi) : "l"(v));
}
__device__ __forceinline__ void ffma2(ull& acc, ull a, ull b) {
    asm("fma.rn.f32x2 %0, %1, %2, %0;" : "+l"(acc) : "l"(a), "l"(b));
}
__device__ __forceinline__ ull fmul2(ull a, ull b) {
    ull d;
    asm("mul.rn.f32x2 %0, %1, %2;" : "=l"(d) : "l"(a), "l"(b));
    return d;
}

// Gaussian(11, sigma=1.5), normalized.
#define G_LIST { \
    0.00102838f, 0.00759875f, 0.03600077f, 0.10936070f, 0.21300553f, \
    0.26601172f, \
    0.21300553f, 0.10936070f, 0.03600077f, 0.00759875f, 0.00102838f }

// TW: tile width, TH: tile height, RPT: rows/thread in V-pass,
// DO_FIN: fold the final loss computation into this kernel (s3 launch).
template<int TW, int TH, int RPT, int DO_FIN>
__global__ void __launch_bounds__(TW * TH / RPT)
ssim_kernel(const float* __restrict__ A0, const float* __restrict__ B0,
            float* __restrict__ out, int scale, int W, int do_pool)
{
    constexpr int NT    = TW * TH / RPT;  // threads per block
    constexpr int IH    = TH + 10;        // rows incl. halo
    constexpr int LW4   = TW / 4 + 4;     // raw-float4 loads per row (scale 0)
    constexpr int NF4   = TW / 2 + 8;     // float4 (=2px) loads per row (pooled)
    constexpr int LP    = 4 * LW4 + 2;    // sSD pitch (row 400/272B: quad-rotating)
    constexpr int SLOTS = TW / 8;         // 8-wide output groups per row
    constexpr int HP    = TW + 1;         // h12 pitch (row 528/272B: quad-rotating)

    __shared__ __align__(16) float2 sSD[IH][LP];       // (s, d) per pixel
    __shared__ __align__(16) ulonglong2 h12[IH][HP];   // {conv(s,d), conv(s^2,d^2)}
    __shared__ float red[NT / 32];

    const float G[11] = G_LIST;
    ull g2[11];
    #pragma unroll
    for (int k = 0; k < 11; k++) g2[k] = pack2(G[k], G[k]);

    const int H = W;
    const float2* P;
    switch (scale) {
        case 1:  P = g_p1; break;
        case 2:  P = g_p2; break;
        default: P = g_p3; break;
    }

    const int tx    = blockIdx.x * TW;
    const int ty    = blockIdx.y * TH;
    const int plane = blockIdx.z;
    const size_t pbase = (size_t)plane * (size_t)W * (size_t)H;
    const int tid = threadIdx.x;

    // ---- stage 1: load tile + halo as interleaved (s,d) ----
    if (scale == 0) {
        for (int i = tid; i < IH * LW4; i += NT) {
            int r = i / LW4;
            int s = i - r * LW4;
            int gy = ty + r - 5;
            int gx = tx + 4 * s - 8;
            float4 a = make_float4(0.f, 0.f, 0.f, 0.f);
            float4 b = a;
            if ((unsigned)gy < (unsigned)H && (unsigned)gx <= (unsigned)(W - 4)) {
                size_t idx = pbase + (size_t)gy * W + gx;
                a = *reinterpret_cast<const float4*>(A0 + idx);
                b = *reinterpret_cast<const float4*>(B0 + idx);
            }
            float4 lo = make_float4(a.x + b.x, a.x - b.x, a.y + b.y, a.y - b.y);
            float4 hi = make_float4(a.z + b.z, a.z - b.z, a.w + b.w, a.w - b.w);
            *reinterpret_cast<float4*>(&sSD[r][4 * s])     = lo;
            *reinterpret_cast<float4*>(&sSD[r][4 * s + 2]) = hi;
        }
    } else {
        for (int i = tid; i < IH * NF4; i += NT) {
            int r = i / NF4;
            int s = i - r * NF4;
            int gy = ty + r - 5;
            int gx = tx + 2 * s - 8;
            float4 v = make_float4(0.f, 0.f, 0.f, 0.f);
            if ((unsigned)gy < (unsigned)H && (unsigned)gx <= (unsigned)(W - 2)) {
                v = *reinterpret_cast<const float4*>(P + pbase + (size_t)gy * W + gx);
            }
            *reinterpret_cast<float4*>(&sSD[r][2 * s]) = v;
        }
    }
    __syncthreads();

    // ---- fused 2x2 avg-pool for the next scale ((s,d) is linear) ----
    if (do_pool) {
        constexpr int PW = TW / 2, PH = TH / 2;
        float2* PD = (scale == 0) ? g_p1 : (scale == 1) ? g_p2 : g_p3;
        int pW = W >> 1;
        for (int i = tid; i < PW * PH; i += NT) {
            int pr = i / PW;
            int pc = i - pr * PW;
            int r = 5 + 2 * pr;
            int c = 8 + 2 * pc;
            float2 q00 = sSD[r][c],     q01 = sSD[r][c + 1];
            float2 q10 = sSD[r + 1][c], q11 = sSD[r + 1][c + 1];
            float2 o;
            o.x = 0.25f * (q00.x + q01.x + q10.x + q11.x);
            o.y = 0.25f * (q00.y + q01.y + q10.y + q11.y);
            size_t pidx = (size_t)plane * pW * pW
                        + (size_t)((ty >> 1) + pr) * pW + ((tx >> 1) + pc);
            PD[pidx] = o;
        }
    }

    // ---- stage 2: horizontal 11-tap pass, 8 outputs/thread-group ----
    // row-fastest map: consecutive lanes -> consecutive rows -> conflict-free.
    for (int i = tid; i < IH * SLOTS; i += NT) {
        int r  = i % IH;
        int sl = i / IH;
        int c0 = 8 * sl;
        ull w[20];   // cols c0+2 .. c0+21
        #pragma unroll
        for (int q = 0; q < 10; q++) {
            ulonglong2 u = *reinterpret_cast<const ulonglong2*>(&sSD[r][c0 + 2 + 2 * q]);
            w[2 * q]     = u.x;
            w[2 * q + 1] = u.y;
        }
        ull a1[8], a2[8];
        #pragma unroll
        for (int j = 0; j < 8; j++) { a1[j] = 0ull; a2[j] = 0ull; }
        #pragma unroll
        for (int m = 0; m < 18; m++) {   // col c0+3+m = w[m+1]
            ull v  = w[m + 1];
            ull v2 = fmul2(v, v);
            #pragma unroll
            for (int j = 0; j < 8; j++) {
                int k = m - j;
                if (k >= 0 && k < 11) {
                    ffma2(a1[j], v,  g2[k]);
                    ffma2(a2[j], v2, g2[k]);
                }
            }
        }
        #pragma unroll
        for (int j = 0; j < 8; j++) {
            h12[r][c0 + j] = make_ulonglong2(a1[j], a2[j]);
        }
    }
    __syncthreads();

    // ---- stage 3: vertical 11-tap pass (f32x2), SSIM map, reduce ----
    float acc = 0.0f;
    {
        const int c  = tid % TW;
        const int r0 = (tid / TW) * RPT;
        ull s1[RPT], s2[RPT];
        #pragma unroll
        for (int j = 0; j < RPT; j++) { s1[j] = 0ull; s2[j] = 0ull; }
        #pragma unroll
        for (int t = 0; t < RPT + 10; t++) {
            ulonglong2 v = h12[r0 + t][c];
            #pragma unroll
            for (int j = 0; j < RPT; j++) {
                int k = t - j;
                if (k >= 0 && k < 11) {
                    ffma2(s1[j], v.x, g2[k]);
                    ffma2(s2[j], v.y, g2[k]);
                }
            }
        }
        const float C1 = 1e-4f;
        const float C2 = 9e-4f;
        #pragma unroll
        for (int j = 0; j < RPT; j++) {
            float mus, mud, es2, ed2;
            unpack2(s1[j], mus, mud);
            unpack2(s2[j], es2, ed2);
            float Aq = mus * mus;
            float Bq = mud * mud;
            float mu12  = 0.25f * (Aq - Bq);            // mu1*mu2
            float musq  = 0.5f  * (Aq + Bq);            // mu1^2+mu2^2
            float sigs  = 0.5f  * (es2 + ed2) - musq;   // sig1^2+sig2^2
            float sig12 = 0.25f * (es2 - ed2) - mu12;   // sig12
            float num = (2.0f * mu12 + C1) * (2.0f * sig12 + C2);
            float den = (musq + C1) * (sigs + C2);
            acc += __fdividef(num, den);
        }
    }

    // ---- block reduction -> one atomic per block ----
    #pragma unroll
    for (int o = 16; o > 0; o >>= 1)
        acc += __shfl_down_sync(0xffffffffu, acc, o);
    if ((tid & 31) == 0) red[tid >> 5] = acc;
    __syncthreads();
    if (tid == 0) {
        float s = 0.f;
        #pragma unroll
        for (int w = 0; w < NT / 32; w++) s += red[w];
        atomicAdd(&g_acc[scale], s);

        if (DO_FIN) {
            __threadfence();                  // order g_acc add before count
            int nblocks = gridDim.x * gridDim.y * gridDim.z;
            int d = atomicAdd(&g_fdone, 1);
            if (d == nblocks - 1) {           // last s3 block: finalize + reset
                float a0 = atomicAdd(&g_acc[0], 0.0f);
                float a1 = atomicAdd(&g_acc[1], 0.0f);
                float a2 = atomicAdd(&g_acc[2], 0.0f);
                float a3 = atomicAdd(&g_acc[3], 0.0f);
                const float wgt[4] = {0.0448f, 0.2856f, 0.3001f, 0.2363f};
                float n0 = 48.0f * 512.0f * 512.0f;
                out[0] = wgt[0] * (1.0f - a0 / n0)
                       + wgt[1] * (1.0f - a1 / (n0 * 0.25f))
                       + wgt[2] * (1.0f - a2 / (n0 * 0.0625f))
                       + wgt[3] * (1.0f - a3 / (n0 * 0.015625f));
                #pragma unroll
                for (int s4 = 0; s4 < 4; s4++) g_acc[s4] = 0.0f;
                g_fdone = 0;                  // reset for next graph replay
            }
        }
    }
}

extern "C" void kernel_launch(void* const* d_in, const int* in_sizes, int n_in,
                              void* d_out, int out_size) {
    const float* img1 = (const float*)d_in[0];
    const float* img2 = (const float*)d_in[1];
    float* out = (float*)d_out;

    // scale 0: 512x512, 32x32 tiles, 256 thr (RPT=4) -> 40 warps/SM
    ssim_kernel<32, 32, 4, 0><<<dim3(16, 16, NPLANES), 256>>>(img1, img2, nullptr, 0, 512, 1);
    // scale 1: 256x256, same config
    ssim_kernel<32, 32, 4, 0><<<dim3(8, 8, NPLANES), 256>>>(nullptr, nullptr, nullptr, 1, 256, 1);
    // scale 2: 128x128, 32x16 tiles, 128 thr (RPT=4)
    ssim_kernel<32, 16, 4, 0><<<dim3(4, 8, NPLANES), 128>>>(nullptr, nullptr, nullptr, 2, 128, 1);
    // scale 3: 64x64, 16x16 tiles, 128 thr (RPT=2), finalize folded in
    ssim_kernel<16, 16, 2, 1><<<dim3(4, 4, NPLANES), 128>>>(nullptr, nullptr, out, 3, 64, 0);
}

// round 12
// speedup vs baseline: 1.0949x; 1.0565x over previous
#include <cuda_runtime.h>

// MS-SSIM loss, 4 scales. v11: TWO launches.
//  A: scale 0 (SSIM + pool -> g_p1).
//  B: scales 1+2+3 UNIFIED and independent: s2/s3 blocks build their input
//     tiles by pooling g_p1 directly (2x2 / 4x4) in stage 1, so there are no
//     cross-scale dependencies, no spins, no launch gaps. Finalize folded
//     into B's last block.
// Math: f32x2 sum/diff form (s=a+b, d=a-b; conv (s,d) and (s^2,d^2)).

#define NPLANES 48
typedef unsigned long long ull;

// ---- device globals (no allocations allowed; zero-init at load) ----
__device__ float  g_acc[4];
__device__ int    g_fdone;
__device__ float2 g_p1[48 * 256 * 256];   // scale-1 (s,d) image

// ---- packed f32x2 helpers ----
__device__ __forceinline__ ull pack2(float lo, float hi) {
    ull r;
    asm("mov.b64 %0, {%1, %2};" : "=l"(r) : "f"(lo), "f"(hi));
    return r;
}
__device__ __forceinline__ void unpack2(ull v, float& lo, float& hi) {
    asm("mov.b64 {%0, %1}, %2;" : "=f"(lo), "=f"(hi) : "l"(v));
}
__device__ __forceinline__ void ffma2(ull& acc, ull a, ull b) {
    asm("fma.rn.f32x2 %0, %1, %2, %0;" : "+l"(acc) : "l"(a), "l"(b));
}
__device__ __forceinline__ ull fmul2(ull a, ull b) {
    ull d;
    asm("mul.rn.f32x2 %0, %1, %2;" : "=l"(d) : "l"(a), "l"(b));
    return d;
}

// Gaussian(11, sigma=1.5), normalized.
#define G_LIST { \
    0.00102838f, 0.00759875f, 0.03600077f, 0.10936070f, 0.21300553f, \
    0.26601172f, \
    0.21300553f, 0.10936070f, 0.03600077f, 0.00759875f, 0.00102838f }

// Unified tile config: 32x32 outputs, 256 threads, RPT=4 (40 warps/SM).
#define TW 32
#define TH 32
#define RPT 4
#define NT 256
#define IH 42                 // TH + 10
#define LW4 12                // TW/4+4 raw-float4 loads per row (scale 0)
#define NF4 24                // TW/2+8 float4(=2px) loads per row (s1 direct)
#define LP 50                 // sSD pitch (row 400B: quad-rotating banks)
#define SLOTS 4               // TW/8 8-wide output groups per row
#define HP 33                 // h12 pitch (row 528B: quad-rotating banks)

// Launch-B block ranges
#define B_S1 3072             // 8x8 tiles x 48 planes (256x256)
#define B_S2 768              // 4x4 tiles x 48 planes (128x128)
#define B_S3 192              // 2x2 tiles x 48 planes (64x64)
#define B_TOT (B_S1 + B_S2 + B_S3)   // 4032

// ---- stages 2+3 (H-pass, V-pass, SSIM, block reduce) — shared ----
__device__ __forceinline__ float stages23(
    float2 (*sSD)[LP], ulonglong2 (*h12)[HP], float* red, const ull* g2)
{
    const int tid = threadIdx.x;

    // stage 2: horizontal 11-tap, 8 outputs/group, row-fastest (conflict-free)
    for (int i = tid; i < IH * SLOTS; i += NT) {
        int r  = i % IH;
        int sl = i / IH;
        int c0 = 8 * sl;
        ull w[20];   // cols c0+2 .. c0+21
        #pragma unroll
        for (int q = 0; q < 10; q++) {
            ulonglong2 u = *reinterpret_cast<const ulonglong2*>(&sSD[r][c0 + 2 + 2 * q]);
            w[2 * q]     = u.x;
            w[2 * q + 1] = u.y;
        }
        ull a1[8], a2[8];
        #pragma unroll
        for (int j = 0; j < 8; j++) { a1[j] = 0ull; a2[j] = 0ull; }
        #pragma unroll
        for (int m = 0; m < 18; m++) {   // col c0+3+m = w[m+1]
            ull v  = w[m + 1];
            ull v2 = fmul2(v, v);
            #pragma unroll
            for (int j = 0; j < 8; j++) {
                int k = m - j;
                if (k >= 0 && k < 11) {
                    ffma2(a1[j], v,  g2[k]);
                    ffma2(a2[j], v2, g2[k]);
                }
            }
        }
        #pragma unroll
        for (int j = 0; j < 8; j++) {
            h12[r][c0 + j] = make_ulonglong2(a1[j], a2[j]);
        }
    }
    __syncthreads();

    // stage 3: vertical 11-tap + SSIM map
    float acc = 0.0f;
    {
        const int c  = tid % TW;
        const int r0 = (tid / TW) * RPT;
        ull s1[RPT], s2[RPT];
        #pragma unroll
        for (int j = 0; j < RPT; j++) { s1[j] = 0ull; s2[j] = 0ull; }
        #pragma unroll
        for (int t = 0; t < RPT + 10; t++) {
            ulonglong2 v = h12[r0 + t][c];
            #pragma unroll
            for (int j = 0; j < RPT; j++) {
                int k = t - j;
                if (k >= 0 && k < 11) {
                    ffma2(s1[j], v.x, g2[k]);
                    ffma2(s2[j], v.y, g2[k]);
                }
            }
        }
        const float C1 = 1e-4f;
        const float C2 = 9e-4f;
        #pragma unroll
        for (int j = 0; j < RPT; j++) {
            float mus, mud, es2, ed2;
            unpack2(s1[j], mus, mud);
            unpack2(s2[j], es2, ed2);
            float Aq = mus * mus;
            float Bq = mud * mud;
            float mu12  = 0.25f * (Aq - Bq);            // mu1*mu2
            float musq  = 0.5f  * (Aq + Bq);            // mu1^2+mu2^2
            float sigs  = 0.5f  * (es2 + ed2) - musq;   // sig1^2+sig2^2
            float sig12 = 0.25f * (es2 - ed2) - mu12;   // sig12
            float num = (2.0f * mu12 + C1) * (2.0f * sig12 + C2);
            float den = (musq + C1) * (sigs + C2);
            acc += __fdividef(num, den);
        }
    }

    // block reduction
    #pragma unroll
    for (int o = 16; o > 0; o >>= 1)
        acc += __shfl_down_sync(0xffffffffu, acc, o);
    if ((tid & 31) == 0) red[tid >> 5] = acc;
    __syncthreads();
    float s = 0.f;
    if (tid == 0) {
        #pragma unroll
        for (int w = 0; w < NT / 32; w++) s += red[w];
    }
    return s;   // valid on tid 0 only
}

// ---- launch A: scale 0 (SSIM + pool -> g_p1) ----
__global__ void __launch_bounds__(NT)
ssim_scale0(const float* __restrict__ A0, const float* __restrict__ B0)
{
    __shared__ __align__(16) float2 sSD[IH][LP];
    __shared__ __align__(16) ulonglong2 h12[IH][HP];
    __shared__ float red[NT / 32];

    const float G[11] = G_LIST;
    ull g2[11];
    #pragma unroll
    for (int k = 0; k < 11; k++) g2[k] = pack2(G[k], G[k]);

    const int tid   = threadIdx.x;
    const int tx    = blockIdx.x * TW;
    const int ty    = blockIdx.y * TH;
    const int plane = blockIdx.z;
    const int W = 512, H = 512;
    const size_t pbase = (size_t)plane * W * H;

    // stage 1: load raw tile + halo, transform to interleaved (s,d)
    for (int i = tid; i < IH * LW4; i += NT) {
        int r = i / LW4;
        int s = i - r * LW4;
        int gy = ty + r - 5;
        int gx = tx + 4 * s - 8;
        float4 a = make_float4(0.f, 0.f, 0.f, 0.f);
        float4 b = a;
        if ((unsigned)gy < (unsigned)H && (unsigned)gx <= (unsigned)(W - 4)) {
            size_t idx = pbase + (size_t)gy * W + gx;
            a = *reinterpret_cast<const float4*>(A0 + idx);
            b = *reinterpret_cast<const float4*>(B0 + idx);
        }
        float4 lo = make_float4(a.x + b.x, a.x - b.x, a.y + b.y, a.y - b.y);
        float4 hi = make_float4(a.z + b.z, a.z - b.z, a.w + b.w, a.w - b.w);
        *reinterpret_cast<float4*>(&sSD[r][4 * s])     = lo;
        *reinterpret_cast<float4*>(&sSD[r][4 * s + 2]) = hi;
    }
    __syncthreads();

    // fused 2x2 avg-pool -> g_p1 (scale-1 image)
    {
        constexpr int PW = TW / 2, PH = TH / 2;
        for (int i = tid; i < PW * PH; i += NT) {
            int pr = i / PW;
            int pc = i - pr * PW;
            int r = 5 + 2 * pr;
            int c = 8 + 2 * pc;
            float2 q00 = sSD[r][c],     q01 = sSD[r][c + 1];
            float2 q10 = sSD[r + 1][c], q11 = sSD[r + 1][c + 1];
            float2 o;
            o.x = 0.25f * (q00.x + q01.x + q10.x + q11.x);
            o.y = 0.25f * (q00.y + q01.y + q10.y + q11.y);
            size_t pidx = (size_t)plane * 256 * 256
                        + (size_t)((ty >> 1) + pr) * 256 + ((tx >> 1) + pc);
            g_p1[pidx] = o;
        }
    }

    float s = stages23(sSD, h12, red, g2);
    if (tid == 0) atomicAdd(&g_acc[0], s);
}

// ---- launch B: scales 1+2+3, all independent given g_p1 ----
__global__ void __launch_bounds__(NT)
ssim_small(float* __restrict__ out)
{
    __shared__ __align__(16) float2 sSD[IH][LP];
    __shared__ __align__(16) ulonglong2 h12[IH][HP];
    __shared__ float red[NT / 32];

    const float G[11] = G_LIST;
    ull g2[11];
    #pragma unroll
    for (int k = 0; k < 11; k++) g2[k] = pack2(G[k], G[k]);

    const int bid = blockIdx.x;
    const int tid = threadIdx.x;

    int scale, plane, txi, tyi, W;
    if (bid < B_S1) {
        scale = 1; W = 256;
        plane = bid >> 6; int rem = bid & 63; tyi = rem >> 3; txi = rem & 7;
    } else if (bid < B_S1 + B_S2) {
        int r = bid - B_S1;
        scale = 2; W = 128;
        plane = r >> 4; int rem = r & 15; tyi = rem >> 2; txi = rem & 3;
    } else {
        int r = bid - (B_S1 + B_S2);
        scale = 3; W = 64;
        plane = r >> 2; int rem = r & 3; tyi = rem >> 1; txi = rem & 1;
    }
    const int H = W;
    const int tx = txi * TW;
    const int ty = tyi * TH;
    const size_t p1base = (size_t)plane * 256 * 256;
    const float2* __restrict__ P1 = g_p1;

    // ---- stage 1: build the scale-s (s,d) tile from g_p1 ----
    if (scale == 1) {
        // direct float4 (2px) loads
        for (int i = tid; i < IH * NF4; i += NT) {
            int r = i / NF4;
            int s = i - r * NF4;
            int gy = ty + r - 5;
            int gx = tx + 2 * s - 8;
            float4 v = make_float4(0.f, 0.f, 0.f, 0.f);
            if ((unsigned)gy < 256u && (unsigned)gx <= (unsigned)(256 - 2)) {
                v = *reinterpret_cast<const float4*>(P1 + p1base + (size_t)gy * 256 + gx);
            }
            *reinterpret_cast<float4*>(&sSD[r][2 * s]) = v;
        }
    } else if (scale == 2) {
        // 2x2 pool of g_p1 per pixel
        for (int i = tid; i < IH * 48; i += NT) {
            int r = i / 48;
            int c = i - r * 48;
            int gy = ty + r - 5;
            int gx = tx + c - 8;
            float2 o = make_float2(0.f, 0.f);
            if ((unsigned)gy < (unsigned)H && (unsigned)gx < (unsigned)W) {
                const float4* row0 = reinterpret_cast<const float4*>(
                    P1 + p1base + (size_t)(2 * gy) * 256 + 2 * gx);
                const float4* row1 = reinterpret_cast<const float4*>(
                    P1 + p1base + (size_t)(2 * gy + 1) * 256 + 2 * gx);
                float4 r0 = *row0;
                float4 r1 = *row1;
                o.x = 0.25f * (r0.x + r0.z + r1.x + r1.z);
                o.y = 0.25f * (r0.y + r0.w + r1.y + r1.w);
            }
            sSD[r][c] = o;
        }
    } else {
        // 4x4 pool of g_p1 per pixel (pool-of-pool order matches reference)
        for (int i = tid; i < IH * 48; i += NT) {
            int r = i / 48;
            int c = i - r * 48;
            int gy = ty + r - 5;
            int gx = tx + c - 8;
            float2 o = make_float2(0.f, 0.f);
            if ((unsigned)gy < (unsigned)H && (unsigned)gx < (unsigned)W) {
                float qx[4], qy[4];   // the four scale-2 pixels
                #pragma unroll
                for (int dy = 0; dy < 2; dy++) {
                    #pragma unroll
                    for (int dx = 0; dx < 2; dx++) {
                        int sy = 4 * gy + 2 * dy;
                        int sx = 4 * gx + 2 * dx;
                        float4 r0 = *reinterpret_cast<const float4*>(
                            P1 + p1base + (size_t)sy * 256 + sx);
                        float4 r1 = *reinterpret_cast<const float4*>(
                            P1 + p1base + (size_t)(sy + 1) * 256 + sx);
                        qx[2 * dy + dx] = 0.25f * (r0.x + r0.z + r1.x + r1.z);
                        qy[2 * dy + dx] = 0.25f * (r0.y + r0.w + r1.y + r1.w);
                    }
                }
                o.x = 0.25f * (qx[0] + qx[1] + qx[2] + qx[3]);
                o.y = 0.25f * (qy[0] + qy[1] + qy[2] + qy[3]);
            }
            sSD[r][c] = o;
        }
    }
    __syncthreads();

    float s = stages23(sSD, h12, red, g2);
    if (tid == 0) {
        atomicAdd(&g_acc[scale], s);
        __threadfence();                  // order g_acc add before count
        int d = atomicAdd(&g_fdone, 1);
        if (d == B_TOT - 1) {             // last block: finalize + reset
            float a0 = atomicAdd(&g_acc[0], 0.0f);
            float a1 = atomicAdd(&g_acc[1], 0.0f);
            float a2 = atomicAdd(&g_acc[2], 0.0f);
            float a3 = atomicAdd(&g_acc[3], 0.0f);
            const float wgt[4] = {0.0448f, 0.2856f, 0.3001f, 0.2363f};
            float n0 = 48.0f * 512.0f * 512.0f;
            out[0] = wgt[0] * (1.0f - a0 / n0)
                   + wgt[1] * (1.0f - a1 / (n0 * 0.25f))
                   + wgt[2] * (1.0f - a2 / (n0 * 0.0625f))
                   + wgt[3] * (1.0f - a3 / (n0 * 0.015625f));
            #pragma unroll
            for (int s4 = 0; s4 < 4; s4++) g_acc[s4] = 0.0f;
            g_fdone = 0;                  // reset for next graph replay
        }
    }
}

extern "C" void kernel_launch(void* const* d_in, const int* in_sizes, int n_in,
                              void* d_out, int out_size) {
    const float* img1 = (const float*)d_in[0];
    const float* img2 = (const float*)d_in[1];
    float* out = (float*)d_out;

    // A: scale 0 (512x512, 32x32 tiles)
    ssim_scale0<<<dim3(16, 16, NPLANES), NT>>>(img1, img2);
    // B: scales 1+2+3, fully independent, finalize folded in
    ssim_small<<<B_TOT, NT>>>(out);
}

// round 13
// speedup vs baseline: 1.1287x; 1.0308x over previous
#include <cuda_runtime.h>

// MS-SSIM loss, 4 scales. v12: v11 structure +
//  - __launch_bounds__(256,5): 5 blocks/SM (40 warps) instead of 4
//  - stage-2 window in two 5-load phases (halves live regs, enables the cap)
//  - kernel A: pool runs on the 88 stage-2-idle threads, off the critical path
// Math: f32x2 sum/diff form (s=a+b, d=a-b; conv (s,d) and (s^2,d^2)).

#define NPLANES 48
typedef unsigned long long ull;

// ---- device globals (no allocations allowed; zero-init at load) ----
__device__ float  g_acc[4];
__device__ int    g_fdone;
__device__ float2 g_p1[48 * 256 * 256];   // scale-1 (s,d) image

// ---- packed f32x2 helpers ----
__device__ __forceinline__ ull pack2(float lo, float hi) {
    ull r;
    asm("mov.b64 %0, {%1, %2};" : "=l"(r) : "f"(lo), "f"(hi));
    return r;
}
__device__ __forceinline__ void unpack2(ull v, float& lo, float& hi) {
    asm("mov.b64 {%0, %1}, %2;" : "=f"(lo), "=f"(hi) : "l"(v));
}
__device__ __forceinline__ void ffma2(ull& acc, ull a, ull b) {
    asm("fma.rn.f32x2 %0, %1, %2, %0;" : "+l"(acc) : "l"(a), "l"(b));
}
__device__ __forceinline__ ull fmul2(ull a, ull b) {
    ull d;
    asm("mul.rn.f32x2 %0, %1, %2;" : "=l"(d) : "l"(a), "l"(b));
    return d;
}

// Gaussian(11, sigma=1.5), normalized.
#define G_LIST { \
    0.00102838f, 0.00759875f, 0.03600077f, 0.10936070f, 0.21300553f, \
    0.26601172f, \
    0.21300553f, 0.10936070f, 0.03600077f, 0.00759875f, 0.00102838f }

// Unified tile config: 32x32 outputs, 256 threads, RPT=4.
#define TW 32
#define TH 32
#define RPT 4
#define NT 256
#define IH 42                 // TH + 10
#define LW4 12                // TW/4+4 raw-float4 loads per row (scale 0)
#define NF4 24                // TW/2+8 float4(=2px) loads per row (s1 direct)
#define LP 50                 // sSD pitch (row 400B: quad-rotating banks)
#define SLOTS 4               // TW/8 8-wide output groups per row
#define NGRP (IH * SLOTS)     // 168 H-pass groups
#define HP 33                 // h12 pitch (row 528B: quad-rotating banks)

// Launch-B block ranges
#define B_S1 3072
#define B_S2 768
#define B_S3 192
#define B_TOT (B_S1 + B_S2 + B_S3)   // 4032

// ---- one 8-wide H-pass group (two 5-load phases, bounded live regs) ----
__device__ __forceinline__ void h_group(
    float2 (*sSD)[LP], ulonglong2 (*h12)[HP], const ull* g2, int i)
{
    int r  = i % IH;               // row-fastest: conflict-free LDS phases
    int sl = i / IH;
    int c0 = 8 * sl;
    ull a1[8], a2[8];
    #pragma unroll
    for (int j = 0; j < 8; j++) { a1[j] = 0ull; a2[j] = 0ull; }
    {
        ull w[10];                 // cols c0+2 .. c0+11
        #pragma unroll
        for (int q = 0; q < 5; q++) {
            ulonglong2 u = *reinterpret_cast<const ulonglong2*>(&sSD[r][c0 + 2 + 2 * q]);
            w[2 * q] = u.x; w[2 * q + 1] = u.y;
        }
        #pragma unroll
        for (int m = 0; m < 9; m++) {    // col c0+3+m = w[m+1]
            ull v  = w[m + 1];
            ull v2 = fmul2(v, v);
            #pragma unroll
            for (int j = 0; j < 8; j++) {
                int k = m - j;
                if (k >= 0 && k < 11) {
                    ffma2(a1[j], v,  g2[k]);
                    ffma2(a2[j], v2, g2[k]);
                }
            }
        }
    }
    {
        ull w[10];                 // cols c0+12 .. c0+21
        #pragma unroll
        for (int q = 0; q < 5; q++) {
            ulonglong2 u = *reinterpret_cast<const ulonglong2*>(&sSD[r][c0 + 12 + 2 * q]);
            w[2 * q] = u.x; w[2 * q + 1] = u.y;
        }
        #pragma unroll
        for (int m = 9; m < 18; m++) {   // col c0+3+m = w[m-9]
            ull v  = w[m - 9];
            ull v2 = fmul2(v, v);
            #pragma unroll
            for (int j = 0; j < 8; j++) {
                int k = m - j;
                if (k >= 0 && k < 11) {
                    ffma2(a1[j], v,  g2[k]);
                    ffma2(a2[j], v2, g2[k]);
                }
            }
        }
    }
    #pragma unroll
    for (int j = 0; j < 8; j++) {
        h12[r][c0 + j] = make_ulonglong2(a1[j], a2[j]);
    }
}

// ---- stage 3 (V-pass + SSIM) + block reduce; returns block sum on tid 0 ----
__device__ __forceinline__ float v_pass_reduce(
    ulonglong2 (*h12)[HP], float* red, const ull* g2)
{
    const int tid = threadIdx.x;
    float acc = 0.0f;
    {
        const int c  = tid % TW;
        const int r0 = (tid / TW) * RPT;
        ull s1[RPT], s2[RPT];
        #pragma unroll
        for (int j = 0; j < RPT; j++) { s1[j] = 0ull; s2[j] = 0ull; }
        #pragma unroll
        for (int t = 0; t < RPT + 10; t++) {
            ulonglong2 v = h12[r0 + t][c];
            #pragma unroll
            for (int j = 0; j < RPT; j++) {
                int k = t - j;
                if (k >= 0 && k < 11) {
                    ffma2(s1[j], v.x, g2[k]);
                    ffma2(s2[j], v.y, g2[k]);
                }
            }
        }
        const float C1 = 1e-4f;
        const float C2 = 9e-4f;
        #pragma unroll
        for (int j = 0; j < RPT; j++) {
            float mus, mud, es2, ed2;
            unpack2(s1[j], mus, mud);
            unpack2(s2[j], es2, ed2);
            float Aq = mus * mus;
            float Bq = mud * mud;
            float mu12  = 0.25f * (Aq - Bq);
            float musq  = 0.5f  * (Aq + Bq);
            float sigs  = 0.5f  * (es2 + ed2) - musq;
            float sig12 = 0.25f * (es2 - ed2) - mu12;
            float num = (2.0f * mu12 + C1) * (2.0f * sig12 + C2);
            float den = (musq + C1) * (sigs + C2);
            acc += __fdividef(num, den);
        }
    }
    #pragma unroll
    for (int o = 16; o > 0; o >>= 1)
        acc += __shfl_down_sync(0xffffffffu, acc, o);
    if ((tid & 31) == 0) red[tid >> 5] = acc;
    __syncthreads();
    float s = 0.f;
    if (tid == 0) {
        #pragma unroll
        for (int w = 0; w < NT / 32; w++) s += red[w];
    }
    return s;
}

// ---- launch A: scale 0 (SSIM + pool -> g_p1) ----
__global__ void __launch_bounds__(NT, 5)
ssim_scale0(const float* __restrict__ A0, const float* __restrict__ B0)
{
    __shared__ __align__(16) float2 sSD[IH][LP];
    __shared__ __align__(16) ulonglong2 h12[IH][HP];
    __shared__ float red[NT / 32];

    const float G[11] = G_LIST;
    ull g2[11];
    #pragma unroll
    for (int k = 0; k < 11; k++) g2[k] = pack2(G[k], G[k]);

    const int tid   = threadIdx.x;
    const int tx    = blockIdx.x * TW;
    const int ty    = blockIdx.y * TH;
    const int plane = blockIdx.z;
    const int W = 512, H = 512;
    const size_t pbase = (size_t)plane * W * H;

    // stage 1: load raw tile + halo, transform to interleaved (s,d)
    for (int i = tid; i < IH * LW4; i += NT) {
        int r = i / LW4;
        int s = i - r * LW4;
        int gy = ty + r - 5;
        int gx = tx + 4 * s - 8;
        float4 a = make_float4(0.f, 0.f, 0.f, 0.f);
        float4 b = a;
        if ((unsigned)gy < (unsigned)H && (unsigned)gx <= (unsigned)(W - 4)) {
            size_t idx = pbase + (size_t)gy * W + gx;
            a = *reinterpret_cast<const float4*>(A0 + idx);
            b = *reinterpret_cast<const float4*>(B0 + idx);
        }
        float4 lo = make_float4(a.x + b.x, a.x - b.x, a.y + b.y, a.y - b.y);
        float4 hi = make_float4(a.z + b.z, a.z - b.z, a.w + b.w, a.w - b.w);
        *reinterpret_cast<float4*>(&sSD[r][4 * s])     = lo;
        *reinterpret_cast<float4*>(&sSD[r][4 * s + 2]) = hi;
    }
    __syncthreads();

    // stage 2 (threads < NGRP) runs CONCURRENTLY with pool (threads >= NGRP)
    if (tid < NGRP) {
        h_group(sSD, h12, g2, tid);
    } else {
        // 2x2 avg-pool -> g_p1: 256 pixels over 88 threads
        for (int i = tid - NGRP; i < 256; i += NT - NGRP) {
            int pr = i >> 4;
            int pc = i & 15;
            int r = 5 + 2 * pr;
            int c = 8 + 2 * pc;
            float2 q00 = sSD[r][c],     q01 = sSD[r][c + 1];
            float2 q10 = sSD[r + 1][c], q11 = sSD[r + 1][c + 1];
            float2 o;
            o.x = 0.25f * (q00.x + q01.x + q10.x + q11.x);
            o.y = 0.25f * (q00.y + q01.y + q10.y + q11.y);
            size_t pidx = (size_t)plane * 256 * 256
                        + (size_t)((ty >> 1) + pr) * 256 + ((tx >> 1) + pc);
            g_p1[pidx] = o;
        }
    }
    __syncthreads();

    float s = v_pass_reduce(h12, red, g2);
    if (tid == 0) atomicAdd(&g_acc[0], s);
}

// ---- launch B: scales 1+2+3, all independent given g_p1 ----
__global__ void __launch_bounds__(NT, 5)
ssim_small(float* __restrict__ out)
{
    __shared__ __align__(16) float2 sSD[IH][LP];
    __shared__ __align__(16) ulonglong2 h12[IH][HP];
    __shared__ float red[NT / 32];

    const float G[11] = G_LIST;
    ull g2[11];
    #pragma unroll
    for (int k = 0; k < 11; k++) g2[k] = pack2(G[k], G[k]);

    const int bid = blockIdx.x;
    const int tid = threadIdx.x;

    int scale, plane, txi, tyi, W;
    if (bid < B_S1) {
        scale = 1; W = 256;
        plane = bid >> 6; int rem = bid & 63; tyi = rem >> 3; txi = rem & 7;
    } else if (bid < B_S1 + B_S2) {
        int r = bid - B_S1;
        scale = 2; W = 128;
        plane = r >> 4; int rem = r & 15; tyi = rem >> 2; txi = rem & 3;
    } else {
        int r = bid - (B_S1 + B_S2);
        scale = 3; W = 64;
        plane = r >> 2; int rem = r & 3; tyi = rem >> 1; txi = rem & 1;
    }
    const int H = W;
    const int tx = txi * TW;
    const int ty = tyi * TH;
    const size_t p1base = (size_t)plane * 256 * 256;
    const float2* __restrict__ P1 = g_p1;

    // ---- stage 1: build the scale-s (s,d) tile from g_p1 ----
    if (scale == 1) {
        for (int i = tid; i < IH * NF4; i += NT) {
            int r = i / NF4;
            int s = i - r * NF4;
            int gy = ty + r - 5;
            int gx = tx + 2 * s - 8;
            float4 v = make_float4(0.f, 0.f, 0.f, 0.f);
            if ((unsigned)gy < 256u && (unsigned)gx <= (unsigned)(256 - 2)) {
                v = *reinterpret_cast<const float4*>(P1 + p1base + (size_t)gy * 256 + gx);
            }
            *reinterpret_cast<float4*>(&sSD[r][2 * s]) = v;
        }
    } else if (scale == 2) {
        for (int i = tid; i < IH * 48; i += NT) {
            int r = i / 48;
            int c = i - r * 48;
            int gy = ty + r - 5;
            int gx = tx + c - 8;
            float2 o = make_float2(0.f, 0.f);
            if ((unsigned)gy < (unsigned)H && (unsigned)gx < (unsigned)W) {
                float4 r0 = *reinterpret_cast<const float4*>(
                    P1 + p1base + (size_t)(2 * gy) * 256 + 2 * gx);
                float4 r1 = *reinterpret_cast<const float4*>(
                    P1 + p1base + (size_t)(2 * gy + 1) * 256 + 2 * gx);
                o.x = 0.25f * (r0.x + r0.z + r1.x + r1.z);
                o.y = 0.25f * (r0.y + r0.w + r1.y + r1.w);
            }
            sSD[r][c] = o;
        }
    } else {
        for (int i = tid; i < IH * 48; i += NT) {
            int r = i / 48;
            int c = i - r * 48;
            int gy = ty + r - 5;
            int gx = tx + c - 8;
            float2 o = make_float2(0.f, 0.f);
            if ((unsigned)gy < (unsigned)H && (unsigned)gx < (unsigned)W) {
                float qx[4], qy[4];
                #pragma unroll
                for (int dy = 0; dy < 2; dy++) {
                    #pragma unroll
                    for (int dx = 0; dx < 2; dx++) {
                        int sy = 4 * gy + 2 * dy;
                        int sx = 4 * gx + 2 * dx;
                        float4 r0 = *reinterpret_cast<const float4*>(
                            P1 + p1base + (size_t)sy * 256 + sx);
                        float4 r1 = *reinterpret_cast<const float4*>(
                            P1 + p1base + (size_t)(sy + 1) * 256 + sx);
                        qx[2 * dy + dx] = 0.25f * (r0.x + r0.z + r1.x + r1.z);
                        qy[2 * dy + dx] = 0.25f * (r0.y + r0.w + r1.y + r1.w);
                    }
                }
                o.x = 0.25f * (qx[0] + qx[1] + qx[2] + qx[3]);
                o.y = 0.25f * (qy[0] + qy[1] + qy[2] + qy[3]);
            }
            sSD[r][c] = o;
        }
    }
    __syncthreads();

    if (tid < NGRP) h_group(sSD, h12, g2, tid);
    __syncthreads();

    float s = v_pass_reduce(h12, red, g2);
    if (tid == 0) {
        atomicAdd(&g_acc[scale], s);
        __threadfence();
        int d = atomicAdd(&g_fdone, 1);
        if (d == B_TOT - 1) {             // last block: finalize + reset
            float a0 = atomicAdd(&g_acc[0], 0.0f);
            float a1 = atomicAdd(&g_acc[1], 0.0f);
            float a2 = atomicAdd(&g_acc[2], 0.0f);
            float a3 = atomicAdd(&g_acc[3], 0.0f);
            const float wgt[4] = {0.0448f, 0.2856f, 0.3001f, 0.2363f};
            float n0 = 48.0f * 512.0f * 512.0f;
            out[0] = wgt[0] * (1.0f - a0 / n0)
                   + wgt[1] * (1.0f - a1 / (n0 * 0.25f))
                   + wgt[2] * (1.0f - a2 / (n0 * 0.0625f))
                   + wgt[3] * (1.0f - a3 / (n0 * 0.015625f));
            #pragma unroll
            for (int s4 = 0; s4 < 4; s4++) g_acc[s4] = 0.0f;
            g_fdone = 0;
        }
    }
}

extern "C" void kernel_launch(void* const* d_in, const int* in_sizes, int n_in,
                              void* d_out, int out_size) {
    const float* img1 = (const float*)d_in[0];
    const float* img2 = (const float*)d_in[1];
    float* out = (float*)d_out;

    ssim_scale0<<<dim3(16, 16, NPLANES), NT>>>(img1, img2);
    ssim_small<<<B_TOT, NT>>>(out);
}